// round 15
// baseline (speedup 1.0000x reference)
#include <cuda_runtime.h>
#include <cuda_bf16.h>
#include <cstdint>

// Problem constants
#define BB 64
#define TT 512
#define EE 2048
#define KK 32
#define MM (BB * TT)
#define CCH 16          // chunks per sequence
#define SCH 32          // steps per chunk

// Scratch (device globals: no allocation allowed)
__device__ float g_logits[MM * KK];          // 4 MB raw logits
__device__ float g_exp[MM * KK];             // 4 MB exp(logits)
__device__ float g_Wt[KK * EE];              // W transposed (tf32-rounded): [n][e]
__device__ float g_M[BB * CCH * KK * KK];    // 4 MB chunk transfer matrices
__device__ float g_sc[BB * CCH];             // chunk log-scales
__device__ float g_ns[BB * CCH];             // chunk valid-step counts
__device__ float g_jnum[BB * CCH];           // chunk joint-score partials
__device__ float g_partial[BB];
__device__ int   g_done = 0;

// ---------------------------------------------------------------------------
// helpers
// ---------------------------------------------------------------------------
static __device__ __forceinline__ float tf32_round(float f) {
    uint32_t r;
    asm("cvt.rna.tf32.f32 %0, %1;" : "=r"(r) : "f"(f));
    return __uint_as_float(r);
}
static __device__ __forceinline__ void mma_tf32(float& c0, float& c1,
                                                float& c2, float& c3,
                                                uint32_t a0, uint32_t a1,
                                                uint32_t a2, uint32_t a3,
                                                uint32_t b0, uint32_t b1) {
    asm volatile(
        "mma.sync.aligned.m16n8k8.row.col.f32.tf32.tf32.f32 "
        "{%0,%1,%2,%3}, {%4,%5,%6,%7}, {%8,%9}, {%0,%1,%2,%3};\n"
        : "+f"(c0), "+f"(c1), "+f"(c2), "+f"(c3)
        : "r"(a0), "r"(a1), "r"(a2), "r"(a3), "r"(b0), "r"(b1));
}
// D = A*B + 0 (separate zero C input; D regs distinct)
static __device__ __forceinline__ void mma_tf32_z(float& d0, float& d1,
                                                  float& d2, float& d3,
                                                  uint32_t a0, uint32_t a1,
                                                  uint32_t a2, uint32_t a3,
                                                  uint32_t b0, uint32_t b1) {
    asm volatile(
        "mma.sync.aligned.m16n8k8.row.col.f32.tf32.tf32.f32 "
        "{%0,%1,%2,%3}, {%4,%5,%6,%7}, {%8,%9}, {%10,%11,%12,%13};\n"
        : "=f"(d0), "=f"(d1), "=f"(d2), "=f"(d3)
        : "r"(a0), "r"(a1), "r"(a2), "r"(a3), "r"(b0), "r"(b1),
          "f"(0.f), "f"(0.f), "f"(0.f), "f"(0.f));
}
static __device__ __forceinline__ void cp_async16(void* dst, const void* src) {
    unsigned sdst = (unsigned)__cvta_generic_to_shared(dst);
    asm volatile("cp.async.cg.shared.global [%0], [%1], 16;\n"
                 :: "r"(sdst), "l"(src));
}
#define CP_COMMIT() asm volatile("cp.async.commit_group;\n" ::: "memory")
#define CP_WAIT0()  asm volatile("cp.async.wait_group 0;\n" ::: "memory")
#define CP_WAIT1()  asm volatile("cp.async.wait_group 1;\n" ::: "memory")
#define CP_WAIT2()  asm volatile("cp.async.wait_group 2;\n" ::: "memory")
#define LN2F 0.6931471805599453f

// ---------------------------------------------------------------------------
// W transpose pre-pass: g_Wt[n][e] = tf32_round(W[e][n])
// ---------------------------------------------------------------------------
__global__ void __launch_bounds__(256) wtrans_kernel(const float* __restrict__ W) {
    __shared__ float s[64][33];
    const int tid = threadIdx.x;
    const int e0 = blockIdx.x * 64;
#pragma unroll
    for (int l = 0; l < 8; l++) {
        int idx = tid + l * 256;
        int ep = idx >> 5, n = idx & 31;
        s[ep][n] = W[(size_t)(e0 + ep) * KK + n];
    }
    __syncthreads();
#pragma unroll
    for (int l = 0; l < 8; l++) {
        int idx = tid + l * 256;
        int n = idx >> 6, ep = idx & 63;
        g_Wt[(size_t)n * EE + e0 + ep] = tf32_round(s[ep][n]);
    }
}

// ---------------------------------------------------------------------------
// GEMM: logits = X @ W + b via mma.sync tf32; writes logits and exp(logits).
// R15: RPB=64, grid 512, 4 STATIC X-buffers (3 tiles in flight), exact
// two-sync-per-tile discipline, proven float2 loadB, mask-prefix CTA skip.
// ---------------------------------------------------------------------------
#define TE 32
#define RPB 64
#define XPITCH 36
#define NBUF 4

__global__ void __launch_bounds__(128) gemm_kernel(const float* __restrict__ X,
                                                   const float* __restrict__ bias,
                                                   const unsigned int* __restrict__ mask) {
    const int row0 = blockIdx.x * RPB;
    // mask is a per-batch prefix: block fully dead iff first timestep masked.
    {
        const int b  = row0 >> 9;         // row0 / TT
        const int t0 = row0 & (TT - 1);
        if (t0 > 0 && mask[b * TT + t0] == 0u) return;
    }

    __shared__ __align__(16) float Xs[NBUF][RPB][XPITCH];   // 36.9 KB static

    const int tid = threadIdx.x;
    const int wid = tid >> 5;
    const int lid = tid & 31;
    const int qr  = lid >> 2;
    const int c   = lid & 3;
    const int rw  = wid * 16;
    const float* Xg = X + (size_t)row0 * EE;
    const int NT = EE / TE;   // 64

    float acc[4][4];
#pragma unroll
    for (int nf = 0; nf < 4; nf++)
#pragma unroll
        for (int u = 0; u < 4; u++) acc[nf][u] = 0.f;

    auto loadX = [&](int bi, int t) {
        const int e0 = t * TE;
#pragma unroll
        for (int l = 0; l < 4; l++) {     // 64 rows x 8 chunks = 512 float4
            int id = tid + l * 128;
            int r  = id >> 3;
            int ch = id & 7;
            cp_async16(&Xs[bi][r][ch * 4], Xg + (size_t)r * EE + e0 + ch * 4);
        }
        CP_COMMIT();
    };
    auto loadB = [&](float2* Bf, int t) {
        const int e0 = t * TE;
#pragma unroll
        for (int ks = 0; ks < 4; ks++)
#pragma unroll
            for (int nf = 0; nf < 4; nf++)
                Bf[ks * 4 + nf] = *(const float2*)(g_Wt +
                    (size_t)(nf * 8 + qr) * EE + e0 + ks * 8 + 2 * c);
    };

    float2 B0f[16], B1f[16];
    loadX(0, 0);
    loadX(1, 1);
    loadX(2, 2);
    loadB(B0f, 0);

    auto step = [&](int t, float2* Bcur, float2* Bnext) {
        loadB(Bnext, min(t + 1, NT - 1));
        // pending groups at entry: tiles t, t+1, t+2 (those that exist)
        if (t < NT - 2)       CP_WAIT2();
        else if (t == NT - 2) CP_WAIT1();
        else                  CP_WAIT0();
        __syncthreads();

        const float (*Xt)[XPITCH] = Xs[t & (NBUF - 1)];
#pragma unroll
        for (int ks = 0; ks < 4; ks++) {
            const int kp = ks * 8 + 2 * c;
            float2 x0 = *(const float2*)&Xt[rw + qr][kp];
            float2 x1 = *(const float2*)&Xt[rw + qr + 8][kp];
#pragma unroll
            for (int nf = 0; nf < 4; nf++) {
                float2 wv = Bcur[ks * 4 + nf];
                mma_tf32(acc[nf][0], acc[nf][1], acc[nf][2], acc[nf][3],
                         __float_as_uint(x0.x), __float_as_uint(x1.x),
                         __float_as_uint(x0.y), __float_as_uint(x1.y),
                         __float_as_uint(wv.x), __float_as_uint(wv.y));
            }
        }
        __syncthreads();
        if (t + 3 < NT) loadX((t + 3) & (NBUF - 1), t + 3);
    };

    for (int t = 0; t < NT; t += 2) {
        step(t, B0f, B1f);
        step(t + 1, B1f, B0f);
    }

    // epilogue: add bias, write logits and exp(logits)
    float bv0[4], bv1[4];
#pragma unroll
    for (int nf = 0; nf < 4; nf++) {
        bv0[nf] = __ldg(bias + nf * 8 + 2 * c);
        bv1[nf] = __ldg(bias + nf * 8 + 2 * c + 1);
    }
    const int rowa = row0 + rw + qr;
    const int rowb = rowa + 8;
    float* loA = g_logits + (size_t)rowa * KK;
    float* loB = g_logits + (size_t)rowb * KK;
    float* eoA = g_exp + (size_t)rowa * KK;
    float* eoB = g_exp + (size_t)rowb * KK;
#pragma unroll
    for (int nf = 0; nf < 4; nf++) {
        int j0 = nf * 8 + 2 * c;
        float2 va = make_float2(acc[nf][0] + bv0[nf], acc[nf][1] + bv1[nf]);
        float2 vb = make_float2(acc[nf][2] + bv0[nf], acc[nf][3] + bv1[nf]);
        *(float2*)(loA + j0) = va;
        *(float2*)(loB + j0) = vb;
        *(float2*)(eoA + j0) = make_float2(__expf(va.x), __expf(va.y));
        *(float2*)(eoB + j0) = make_float2(__expf(vb.x), __expf(vb.y));
    }
}

// ---------------------------------------------------------------------------
// Chunk kernel: warp (b, ch) computes M_c = prod (ET . diag(e_t)) via
// register-resident mma.sync chains, AND this chunk's joint-score partial.
// (exact R12 version)
// ---------------------------------------------------------------------------
__global__ void __launch_bounds__(32) chunk_kernel(const int* __restrict__ y,
                                                   const unsigned int* __restrict__ mask,
                                                   const float* __restrict__ trans,
                                                   const float* __restrict__ startT) {
    __shared__ __align__(16) float Es[SCH * KK];   // chunk emissions (4 KB)

    const int b  = blockIdx.x >> 4;
    const int ch = blockIdx.x & 15;
    const int lid = threadIdx.x;
    const int qr = lid >> 2;
    const int c  = lid & 3;
    const int t0 = ch * SCH + 1;

    // stage emissions for steps t0..t0+31 (rows clamped to <TT)
    const float* EB = g_exp + (size_t)b * TT * KK;
#pragma unroll
    for (int k = 0; k < 8; k++) {
        int f = lid + k * 32;
        int row = f >> 3;
        if (t0 + row < TT)
            cp_async16(&Es[f * 4], EB + (size_t)(t0 + row) * KK + (f & 7) * 4);
    }
    CP_COMMIT();

    const unsigned int* mk = mask + b * TT;
    const int* yb = y + b * TT;

    // ---- joint-score partial for timesteps tt = ch*32 + lid ----
    {
        const int tt = ch * SCH + lid;
        float jp = 0.f;
        if (mk[tt] != 0u) {
            int yt = yb[tt];
            jp = g_logits[(size_t)b * TT * KK + tt * KK + yt];
            if (tt > 0) jp += trans[yb[tt - 1] * KK + yt];
        }
#pragma unroll
        for (int o = 16; o; o >>= 1) jp += __shfl_xor_sync(0xffffffffu, jp, o);
        if (lid == 0) {
            if (ch == 0) jp += startT[yb[0]];
            g_jnum[b * CCH + ch] = jp;
        }
    }

    // ---- chunk-local valid-step count (mask is a prefix) ----
    int v = 0;
    if (t0 + lid < TT) v = (mk[t0 + lid] != 0u);
#pragma unroll
    for (int o = 16; o; o >>= 1) v += __shfl_xor_sync(0xffffffffu, v, o);
    const int ns = v;   // 0..32

    // static ET fragments (tf32-rounded)
    float ETb0[4][4], ETb1[4][4];
#pragma unroll
    for (int ks = 0; ks < 4; ks++)
#pragma unroll
        for (int nf = 0; nf < 4; nf++) {
            ETb0[ks][nf] = tf32_round(__expf(trans[(8 * ks + 2 * c)     * KK + 8 * nf + qr]));
            ETb1[ks][nf] = tf32_round(__expf(trans[(8 * ks + 2 * c + 1) * KK + 8 * nf + qr]));
        }

    // M = I
    float Mr[2][4][4], Nr[2][4][4];
#pragma unroll
    for (int g = 0; g < 2; g++)
#pragma unroll
        for (int nf = 0; nf < 4; nf++) {
            int ra = 16 * g + qr, rb = ra + 8;
            int ca = 8 * nf + 2 * c, cb = ca + 1;
            Mr[g][nf][0] = (ra == ca) ? 1.f : 0.f;
            Mr[g][nf][1] = (ra == cb) ? 1.f : 0.f;
            Mr[g][nf][2] = (rb == ca) ? 1.f : 0.f;
            Mr[g][nf][3] = (rb == cb) ? 1.f : 0.f;
        }
    float s = 0.f;

    auto renormM = [&]() {
        float mx = 0.f;
#pragma unroll
        for (int g = 0; g < 2; g++)
#pragma unroll
            for (int nf = 0; nf < 4; nf++)
#pragma unroll
                for (int u = 0; u < 4; u++) mx = fmaxf(mx, Mr[g][nf][u]);
        unsigned mxb = __reduce_max_sync(0xffffffffu, __float_as_uint(mx));
        unsigned ee = mxb >> 23;
        float scf = __uint_as_float((254u - ee) << 23);
#pragma unroll
        for (int g = 0; g < 2; g++)
#pragma unroll
            for (int nf = 0; nf < 4; nf++)
#pragma unroll
                for (int u = 0; u < 4; u++) Mr[g][nf][u] *= scf;
        s += (float)((int)ee - 127) * LN2F;
    };

    if (ns > 0) {
        CP_WAIT0();
        __syncwarp();

        float eC[4], eN[4];
#pragma unroll
        for (int nf = 0; nf < 4; nf++) eC[nf] = Es[0 * KK + 8 * nf + qr];
        {
            int un = (ns > 1) ? 1 : 0;
#pragma unroll
            for (int nf = 0; nf < 4; nf++) eN[nf] = Es[un * KK + 8 * nf + qr];
        }

        // one scan step: DST = SRC * (ET . diag(e))
        auto do_step = [&](float (&S)[2][4][4], float (&D)[2][4][4]) {
            float B0[4][4], B1[4][4];
#pragma unroll
            for (int ks = 0; ks < 4; ks++)
#pragma unroll
                for (int nf = 0; nf < 4; nf++) {
                    B0[ks][nf] = tf32_round(ETb0[ks][nf] * eC[nf]);
                    B1[ks][nf] = tf32_round(ETb1[ks][nf] * eC[nf]);
                }
#pragma unroll
            for (int g = 0; g < 2; g++)
#pragma unroll
                for (int nf = 0; nf < 4; nf++) {
                    mma_tf32_z(D[g][nf][0], D[g][nf][1], D[g][nf][2], D[g][nf][3],
                               __float_as_uint(S[g][0][0]), __float_as_uint(S[g][0][2]),
                               __float_as_uint(S[g][0][1]), __float_as_uint(S[g][0][3]),
                               __float_as_uint(B0[0][nf]), __float_as_uint(B1[0][nf]));
#pragma unroll
                    for (int ks = 1; ks < 4; ks++)
                        mma_tf32(D[g][nf][0], D[g][nf][1], D[g][nf][2], D[g][nf][3],
                                 __float_as_uint(S[g][ks][0]), __float_as_uint(S[g][ks][2]),
                                 __float_as_uint(S[g][ks][1]), __float_as_uint(S[g][ks][3]),
                                 __float_as_uint(B0[ks][nf]), __float_as_uint(B1[ks][nf]));
                }
        };

#pragma unroll 2
        for (int u = 0; u < ns; u++) {
            if (u & 1) do_step(Nr, Mr);
            else       do_step(Mr, Nr);
#pragma unroll
            for (int nf = 0; nf < 4; nf++) eC[nf] = eN[nf];
            int un = u + 2 < ns ? u + 2 : (ns - 1);
#pragma unroll
            for (int nf = 0; nf < 4; nf++) eN[nf] = Es[un * KK + 8 * nf + qr];
            if (((u + 1) & 7) == 0) renormM();
        }
        if (ns & 1) {
#pragma unroll
            for (int g = 0; g < 2; g++)
#pragma unroll
                for (int nf = 0; nf < 4; nf++)
#pragma unroll
                    for (int u = 0; u < 4; u++) Mr[g][nf][u] = Nr[g][nf][u];
        }
    } else {
        CP_WAIT0();
    }

    // store M_c, scale, and step count
    float* out = g_M + (size_t)(b * CCH + ch) * (KK * KK);
#pragma unroll
    for (int g = 0; g < 2; g++)
#pragma unroll
        for (int nf = 0; nf < 4; nf++) {
            int ra = 16 * g + qr, ca = 8 * nf + 2 * c;
            *(float2*)(out + ra * KK + ca)       = make_float2(Mr[g][nf][0], Mr[g][nf][1]);
            *(float2*)(out + (ra + 8) * KK + ca) = make_float2(Mr[g][nf][2], Mr[g][nf][3]);
        }
    if (lid == 0) {
        g_sc[b * CCH + ch] = s;
        g_ns[b * CCH + ch] = (float)ns;
    }
}

// ---------------------------------------------------------------------------
// Combine kernel: one warp per batch. Sum joint partials (+ derive len from
// chunk step counts) + fold 16 chunk matrices + final logsumexp + reduction.
// (exact R12 version)
// ---------------------------------------------------------------------------
__global__ void __launch_bounds__(32) combine_kernel(const int* __restrict__ y,
                                                     const float* __restrict__ startT,
                                                     const float* __restrict__ endT,
                                                     float* __restrict__ out) {
    __shared__ __align__(16) float Ms[2][KK * KK];

    const int b = blockIdx.x;
    const int j = threadIdx.x;
    const int* yb = y + b * TT;

    // prefetch chunk 0 matrix
    {
        const float* Mc = g_M + (size_t)(b * CCH) * (KK * KK);
#pragma unroll
        for (int k = 0; k < 8; k++)
            cp_async16(&Ms[0][j * 4 + k * 128], Mc + j * 4 + k * 128);
        CP_COMMIT();
    }

    // fused tree: joint partials + scales + step counts (len = 1 + sum ns)
    float num = (j < CCH) ? g_jnum[b * CCH + j] : 0.f;
    float scs = (j < CCH) ? g_sc[b * CCH + j] : 0.f;
    float nsf = (j < CCH) ? g_ns[b * CCH + j] : 0.f;
#pragma unroll
    for (int o = 16; o; o >>= 1) {
        num += __shfl_xor_sync(0xffffffffu, num, o);
        scs += __shfl_xor_sync(0xffffffffu, scs, o);
        nsf += __shfl_xor_sync(0xffffffffu, nsf, o);
    }
    const int len = 1 + (int)nsf;
    if (j == 0) num += endT[yb[len - 1]];

    // alpha0
    float a0 = startT[j] + g_logits[(size_t)b * TT * KK + j];
    float m = a0;
#pragma unroll
    for (int o = 16; o; o >>= 1) m = fmaxf(m, __shfl_xor_sync(0xffffffffu, m, o));
    float p = __expf(a0 - m);
    float s = m + scs;    // all chunk scales folded up-front

    // fold the 16 chunk matrices
    for (int ch = 0; ch < CCH; ch++) {
        if (ch + 1 < CCH) {
            const float* Mn = g_M + (size_t)(b * CCH + ch + 1) * (KK * KK);
#pragma unroll
            for (int k = 0; k < 8; k++)
                cp_async16(&Ms[(ch + 1) & 1][j * 4 + k * 128], Mn + j * 4 + k * 128);
            CP_COMMIT();
            CP_WAIT1();
        } else {
            CP_WAIT0();
        }
        __syncwarp();

        const float* Mc = Ms[ch & 1];
        float r0 = 0.f, r1 = 0.f, r2 = 0.f, r3 = 0.f;
#pragma unroll
        for (int i = 0; i < KK; i += 4) {
            r0 = fmaf(__shfl_sync(0xffffffffu, p, i + 0), Mc[(i + 0) * KK + j], r0);
            r1 = fmaf(__shfl_sync(0xffffffffu, p, i + 1), Mc[(i + 1) * KK + j], r1);
            r2 = fmaf(__shfl_sync(0xffffffffu, p, i + 2), Mc[(i + 2) * KK + j], r2);
            r3 = fmaf(__shfl_sync(0xffffffffu, p, i + 3), Mc[(i + 3) * KK + j], r3);
        }
        p = (r0 + r1) + (r2 + r3);

        unsigned mxb = __reduce_max_sync(0xffffffffu, __float_as_uint(p));
        unsigned ee = mxb >> 23;
        p *= __uint_as_float((254u - ee) << 23);
        s += (float)((int)ee - 127) * LN2F;
        __syncwarp();
    }

    float q = p * __expf(endT[j]);
#pragma unroll
    for (int o = 16; o; o >>= 1) q += __shfl_xor_sync(0xffffffffu, q, o);
    float den = s + __logf(q);

    if (j == 0) g_partial[b] = num - den;

    // fused final reduction: last CTA sums all partials
    __threadfence();
    int lastflag = 0;
    if (j == 0) lastflag = (atomicAdd(&g_done, 1) == BB - 1);
    lastflag = __shfl_sync(0xffffffffu, lastflag, 0);
    if (lastflag) {
        __threadfence();
        float v = g_partial[j] + g_partial[j + 32];
#pragma unroll
        for (int o = 16; o; o >>= 1) v += __shfl_xor_sync(0xffffffffu, v, o);
        if (j == 0) {
            out[0] = -v;
            g_done = 0;   // reset for next graph replay
        }
    }
}

// ---------------------------------------------------------------------------
extern "C" void kernel_launch(void* const* d_in, const int* in_sizes, int n_in,
                              void* d_out, int out_size) {
    const float*         X     = (const float*)d_in[0];
    const int*           y     = (const int*)d_in[1];
    const unsigned int*  mask  = (const unsigned int*)d_in[2];
    const float*         W     = (const float*)d_in[3];
    const float*         bias  = (const float*)d_in[4];
    const float*         trans = (const float*)d_in[5];
    const float*         stt   = (const float*)d_in[6];
    const float*         endt  = (const float*)d_in[7];
    float* out = (float*)d_out;

    wtrans_kernel<<<EE / 64, 256>>>(W);
    gemm_kernel<<<MM / RPB, 128>>>(X, bias, mask);
    chunk_kernel<<<BB * CCH, 32>>>(y, mask, trans, stt);
    combine_kernel<<<BB, 32>>>(y, stt, endt, out);
}

// round 16
// speedup vs baseline: 1.2685x; 1.2685x over previous
#include <cuda_runtime.h>
#include <cuda_bf16.h>
#include <cstdint>

// Problem constants
#define BB 64
#define TT 512
#define EE 2048
#define KK 32
#define MM (BB * TT)
#define CCH 16          // chunks per sequence
#define SCH 32          // steps per chunk

// Scratch (device globals: no allocation allowed)
__device__ float g_logits[MM * KK];          // 4 MB raw logits
__device__ float g_exp[MM * KK];             // 4 MB exp(logits)
__device__ float g_Wt[KK * EE];              // W transposed (tf32-rounded): [n][e]
__device__ float g_M[BB * CCH * KK * KK];    // 4 MB chunk transfer matrices
__device__ float g_sc[BB * CCH];             // chunk log-scales
__device__ float g_ns[BB * CCH];             // chunk valid-step counts
__device__ float g_jnum[BB * CCH];           // chunk joint-score partials
__device__ float g_partial[BB];
__device__ int   g_bdone[BB];                // per-batch chunk arrival counters
__device__ int   g_done = 0;

// ---------------------------------------------------------------------------
// helpers
// ---------------------------------------------------------------------------
static __device__ __forceinline__ float tf32_round(float f) {
    uint32_t r;
    asm("cvt.rna.tf32.f32 %0, %1;" : "=r"(r) : "f"(f));
    return __uint_as_float(r);
}
static __device__ __forceinline__ void mma_tf32(float& c0, float& c1,
                                                float& c2, float& c3,
                                                uint32_t a0, uint32_t a1,
                                                uint32_t a2, uint32_t a3,
                                                uint32_t b0, uint32_t b1) {
    asm volatile(
        "mma.sync.aligned.m16n8k8.row.col.f32.tf32.tf32.f32 "
        "{%0,%1,%2,%3}, {%4,%5,%6,%7}, {%8,%9}, {%0,%1,%2,%3};\n"
        : "+f"(c0), "+f"(c1), "+f"(c2), "+f"(c3)
        : "r"(a0), "r"(a1), "r"(a2), "r"(a3), "r"(b0), "r"(b1));
}
// D = A*B + 0 (separate zero C input; D regs distinct)
static __device__ __forceinline__ void mma_tf32_z(float& d0, float& d1,
                                                  float& d2, float& d3,
                                                  uint32_t a0, uint32_t a1,
                                                  uint32_t a2, uint32_t a3,
                                                  uint32_t b0, uint32_t b1) {
    asm volatile(
        "mma.sync.aligned.m16n8k8.row.col.f32.tf32.tf32.f32 "
        "{%0,%1,%2,%3}, {%4,%5,%6,%7}, {%8,%9}, {%10,%11,%12,%13};\n"
        : "=f"(d0), "=f"(d1), "=f"(d2), "=f"(d3)
        : "r"(a0), "r"(a1), "r"(a2), "r"(a3), "r"(b0), "r"(b1),
          "f"(0.f), "f"(0.f), "f"(0.f), "f"(0.f));
}
static __device__ __forceinline__ void cp_async16(void* dst, const void* src) {
    unsigned sdst = (unsigned)__cvta_generic_to_shared(dst);
    asm volatile("cp.async.cg.shared.global [%0], [%1], 16;\n"
                 :: "r"(sdst), "l"(src));
}
#define CP_COMMIT() asm volatile("cp.async.commit_group;\n" ::: "memory")
#define CP_WAIT0()  asm volatile("cp.async.wait_group 0;\n" ::: "memory")
#define CP_WAIT1()  asm volatile("cp.async.wait_group 1;\n" ::: "memory")
#define LN2F 0.6931471805599453f

// ---------------------------------------------------------------------------
// W transpose pre-pass: g_Wt[n][e] = tf32_round(W[e][n])
// ---------------------------------------------------------------------------
__global__ void __launch_bounds__(256) wtrans_kernel(const float* __restrict__ W) {
    __shared__ float s[64][33];
    const int tid = threadIdx.x;
    const int e0 = blockIdx.x * 64;
#pragma unroll
    for (int l = 0; l < 8; l++) {
        int idx = tid + l * 256;
        int ep = idx >> 5, n = idx & 31;
        s[ep][n] = W[(size_t)(e0 + ep) * KK + n];
    }
    __syncthreads();
#pragma unroll
    for (int l = 0; l < 8; l++) {
        int idx = tid + l * 256;
        int n = idx >> 6, ep = idx & 63;
        g_Wt[(size_t)n * EE + e0 + ep] = tf32_round(s[ep][n]);
    }
}

// ---------------------------------------------------------------------------
// GEMM: logits = X @ W + b via mma.sync tf32; writes logits and exp(logits).
// FROZEN R12 structure (depth-2 cp.async, two syncs/tile) + mask CTA skip.
// ---------------------------------------------------------------------------
#define TE 32
#define RPB 128
#define XPITCH 36

__global__ void __launch_bounds__(128) gemm_kernel(const float* __restrict__ X,
                                                   const float* __restrict__ bias,
                                                   const unsigned int* __restrict__ mask) {
    const int row0 = blockIdx.x * RPB;
    // mask is a per-batch prefix: block fully dead iff first timestep masked.
    {
        const int b  = row0 >> 9;         // row0 / TT
        const int t0 = row0 & (TT - 1);
        if (t0 > 0 && mask[b * TT + t0] == 0u) return;
    }

    __shared__ __align__(16) float Xs[2][RPB][XPITCH];

    const int tid = threadIdx.x;
    const int wid = tid >> 5;
    const int lid = tid & 31;
    const int qr  = lid >> 2;
    const int c   = lid & 3;
    const int rw2 = wid * 32;
    const float* Xg = X + (size_t)row0 * EE;
    const int NT = EE / TE;

    float acc[2][4][4];
#pragma unroll
    for (int g = 0; g < 2; g++)
#pragma unroll
        for (int nf = 0; nf < 4; nf++)
#pragma unroll
            for (int u = 0; u < 4; u++) acc[g][nf][u] = 0.f;

    auto loadX = [&](int bi, int t) {
        const int e0 = t * TE;
#pragma unroll
        for (int l = 0; l < 8; l++) {
            int id = tid + l * 128;
            int r  = id >> 3;
            int ch = id & 7;
            cp_async16(&Xs[bi][r][ch * 4], Xg + (size_t)r * EE + e0 + ch * 4);
        }
    };
    auto loadB = [&](float2* Bf, int t) {
        const int e0 = t * TE;
#pragma unroll
        for (int ks = 0; ks < 4; ks++)
#pragma unroll
            for (int nf = 0; nf < 4; nf++)
                Bf[ks * 4 + nf] = *(const float2*)(g_Wt +
                    (size_t)(nf * 8 + qr) * EE + e0 + ks * 8 + 2 * c);
    };

    float2 B0f[16], B1f[16];
    loadX(0, 0); CP_COMMIT();
    loadX(1, 1); CP_COMMIT();
    loadB(B0f, 0);

    auto step = [&](int t, float2* Bcur, float2* Bnext) {
        loadB(Bnext, min(t + 1, NT - 1));
        if (t < NT - 1) { CP_WAIT1(); } else { CP_WAIT0(); }
        __syncthreads();

        const float (*Xt)[XPITCH] = Xs[t & 1];
#pragma unroll
        for (int ks = 0; ks < 4; ks++) {
            const int kp = ks * 8 + 2 * c;
            float2 x0 = *(const float2*)&Xt[rw2 + qr][kp];
            float2 x1 = *(const float2*)&Xt[rw2 + qr + 8][kp];
            float2 x2 = *(const float2*)&Xt[rw2 + qr + 16][kp];
            float2 x3 = *(const float2*)&Xt[rw2 + qr + 24][kp];
#pragma unroll
            for (int nf = 0; nf < 4; nf++) {
                float2 wv = Bcur[ks * 4 + nf];
                uint32_t b0 = __float_as_uint(wv.x);
                uint32_t b1 = __float_as_uint(wv.y);
                mma_tf32(acc[0][nf][0], acc[0][nf][1], acc[0][nf][2], acc[0][nf][3],
                         __float_as_uint(x0.x), __float_as_uint(x1.x),
                         __float_as_uint(x0.y), __float_as_uint(x1.y), b0, b1);
                mma_tf32(acc[1][nf][0], acc[1][nf][1], acc[1][nf][2], acc[1][nf][3],
                         __float_as_uint(x2.x), __float_as_uint(x3.x),
                         __float_as_uint(x2.y), __float_as_uint(x3.y), b0, b1);
            }
        }
        __syncthreads();
        if (t + 2 < NT) { loadX(t & 1, t + 2); CP_COMMIT(); }
    };

    for (int t = 0; t < NT; t += 2) {
        step(t, B0f, B1f);
        step(t + 1, B1f, B0f);
    }

    float bv0[4], bv1[4];
#pragma unroll
    for (int nf = 0; nf < 4; nf++) {
        bv0[nf] = __ldg(bias + nf * 8 + 2 * c);
        bv1[nf] = __ldg(bias + nf * 8 + 2 * c + 1);
    }
#pragma unroll
    for (int g = 0; g < 2; g++) {
        const int rowa = row0 + rw2 + qr + g * 16;
        const int rowb = rowa + 8;
        float* loA = g_logits + (size_t)rowa * KK;
        float* loB = g_logits + (size_t)rowb * KK;
        float* eoA = g_exp + (size_t)rowa * KK;
        float* eoB = g_exp + (size_t)rowb * KK;
#pragma unroll
        for (int nf = 0; nf < 4; nf++) {
            int j0 = nf * 8 + 2 * c;
            float2 va = make_float2(acc[g][nf][0] + bv0[nf], acc[g][nf][1] + bv1[nf]);
            float2 vb = make_float2(acc[g][nf][2] + bv0[nf], acc[g][nf][3] + bv1[nf]);
            *(float2*)(loA + j0) = va;
            *(float2*)(loB + j0) = vb;
            *(float2*)(eoA + j0) = make_float2(__expf(va.x), __expf(va.y));
            *(float2*)(eoB + j0) = make_float2(__expf(vb.x), __expf(vb.y));
        }
    }
}

// ---------------------------------------------------------------------------
// Chunk kernel (R12 body) + FUSED combine: the 16th-arriving chunk CTA of
// each batch folds that batch's matrices; last batch feeds global reduction.
// ---------------------------------------------------------------------------
__global__ void __launch_bounds__(32) chunk_kernel(const int* __restrict__ y,
                                                   const unsigned int* __restrict__ mask,
                                                   const float* __restrict__ trans,
                                                   const float* __restrict__ startT,
                                                   const float* __restrict__ endT,
                                                   float* __restrict__ out) {
    __shared__ __align__(16) float Es[SCH * KK];   // chunk emissions (4 KB)
    __shared__ __align__(16) float Ms[2][KK * KK]; // combine staging (8 KB)

    const int b  = blockIdx.x >> 4;
    const int ch = blockIdx.x & 15;
    const int lid = threadIdx.x;
    const int qr = lid >> 2;
    const int c  = lid & 3;
    const int t0 = ch * SCH + 1;

    // stage emissions for steps t0..t0+31 (rows clamped to <TT)
    const float* EB = g_exp + (size_t)b * TT * KK;
#pragma unroll
    for (int k = 0; k < 8; k++) {
        int f = lid + k * 32;
        int row = f >> 3;
        if (t0 + row < TT)
            cp_async16(&Es[f * 4], EB + (size_t)(t0 + row) * KK + (f & 7) * 4);
    }
    CP_COMMIT();

    const unsigned int* mk = mask + b * TT;
    const int* yb = y + b * TT;

    // ---- joint-score partial for timesteps tt = ch*32 + lid ----
    {
        const int tt = ch * SCH + lid;
        float jp = 0.f;
        if (mk[tt] != 0u) {
            int yt = yb[tt];
            jp = g_logits[(size_t)b * TT * KK + tt * KK + yt];
            if (tt > 0) jp += trans[yb[tt - 1] * KK + yt];
        }
#pragma unroll
        for (int o = 16; o; o >>= 1) jp += __shfl_xor_sync(0xffffffffu, jp, o);
        if (lid == 0) {
            if (ch == 0) jp += startT[yb[0]];
            g_jnum[b * CCH + ch] = jp;
        }
    }

    // ---- chunk-local valid-step count (mask is a prefix) ----
    int v = 0;
    if (t0 + lid < TT) v = (mk[t0 + lid] != 0u);
#pragma unroll
    for (int o = 16; o; o >>= 1) v += __shfl_xor_sync(0xffffffffu, v, o);
    const int ns = v;   // 0..32

    // static ET fragments (tf32-rounded)
    float ETb0[4][4], ETb1[4][4];
#pragma unroll
    for (int ks = 0; ks < 4; ks++)
#pragma unroll
        for (int nf = 0; nf < 4; nf++) {
            ETb0[ks][nf] = tf32_round(__expf(trans[(8 * ks + 2 * c)     * KK + 8 * nf + qr]));
            ETb1[ks][nf] = tf32_round(__expf(trans[(8 * ks + 2 * c + 1) * KK + 8 * nf + qr]));
        }

    // M = I
    float Mr[2][4][4], Nr[2][4][4];
#pragma unroll
    for (int g = 0; g < 2; g++)
#pragma unroll
        for (int nf = 0; nf < 4; nf++) {
            int ra = 16 * g + qr, rb = ra + 8;
            int ca = 8 * nf + 2 * c, cb = ca + 1;
            Mr[g][nf][0] = (ra == ca) ? 1.f : 0.f;
            Mr[g][nf][1] = (ra == cb) ? 1.f : 0.f;
            Mr[g][nf][2] = (rb == ca) ? 1.f : 0.f;
            Mr[g][nf][3] = (rb == cb) ? 1.f : 0.f;
        }
    float s = 0.f;

    auto renormM = [&]() {
        float mx = 0.f;
#pragma unroll
        for (int g = 0; g < 2; g++)
#pragma unroll
            for (int nf = 0; nf < 4; nf++)
#pragma unroll
                for (int u = 0; u < 4; u++) mx = fmaxf(mx, Mr[g][nf][u]);
        unsigned mxb = __reduce_max_sync(0xffffffffu, __float_as_uint(mx));
        unsigned ee = mxb >> 23;
        float scf = __uint_as_float((254u - ee) << 23);
#pragma unroll
        for (int g = 0; g < 2; g++)
#pragma unroll
            for (int nf = 0; nf < 4; nf++)
#pragma unroll
                for (int u = 0; u < 4; u++) Mr[g][nf][u] *= scf;
        s += (float)((int)ee - 127) * LN2F;
    };

    if (ns > 0) {
        CP_WAIT0();
        __syncwarp();

        float eC[4], eN[4];
#pragma unroll
        for (int nf = 0; nf < 4; nf++) eC[nf] = Es[0 * KK + 8 * nf + qr];
        {
            int un = (ns > 1) ? 1 : 0;
#pragma unroll
            for (int nf = 0; nf < 4; nf++) eN[nf] = Es[un * KK + 8 * nf + qr];
        }

        // one scan step: DST = SRC * (ET . diag(e))
        auto do_step = [&](float (&S)[2][4][4], float (&D)[2][4][4]) {
            float B0[4][4], B1[4][4];
#pragma unroll
            for (int ks = 0; ks < 4; ks++)
#pragma unroll
                for (int nf = 0; nf < 4; nf++) {
                    B0[ks][nf] = tf32_round(ETb0[ks][nf] * eC[nf]);
                    B1[ks][nf] = tf32_round(ETb1[ks][nf] * eC[nf]);
                }
#pragma unroll
            for (int g = 0; g < 2; g++)
#pragma unroll
                for (int nf = 0; nf < 4; nf++) {
                    mma_tf32_z(D[g][nf][0], D[g][nf][1], D[g][nf][2], D[g][nf][3],
                               __float_as_uint(S[g][0][0]), __float_as_uint(S[g][0][2]),
                               __float_as_uint(S[g][0][1]), __float_as_uint(S[g][0][3]),
                               __float_as_uint(B0[0][nf]), __float_as_uint(B1[0][nf]));
#pragma unroll
                    for (int ks = 1; ks < 4; ks++)
                        mma_tf32(D[g][nf][0], D[g][nf][1], D[g][nf][2], D[g][nf][3],
                                 __float_as_uint(S[g][ks][0]), __float_as_uint(S[g][ks][2]),
                                 __float_as_uint(S[g][ks][1]), __float_as_uint(S[g][ks][3]),
                                 __float_as_uint(B0[ks][nf]), __float_as_uint(B1[ks][nf]));
                }
        };

#pragma unroll 2
        for (int u = 0; u < ns; u++) {
            if (u & 1) do_step(Nr, Mr);
            else       do_step(Mr, Nr);
#pragma unroll
            for (int nf = 0; nf < 4; nf++) eC[nf] = eN[nf];
            int un = u + 2 < ns ? u + 2 : (ns - 1);
#pragma unroll
            for (int nf = 0; nf < 4; nf++) eN[nf] = Es[un * KK + 8 * nf + qr];
            if (((u + 1) & 7) == 0) renormM();
        }
        if (ns & 1) {
#pragma unroll
            for (int g = 0; g < 2; g++)
#pragma unroll
                for (int nf = 0; nf < 4; nf++)
#pragma unroll
                    for (int u = 0; u < 4; u++) Mr[g][nf][u] = Nr[g][nf][u];
        }
    } else {
        CP_WAIT0();
    }

    // store M_c, scale, and step count
    float* outM = g_M + (size_t)(b * CCH + ch) * (KK * KK);
#pragma unroll
    for (int g = 0; g < 2; g++)
#pragma unroll
        for (int nf = 0; nf < 4; nf++) {
            int ra = 16 * g + qr, ca = 8 * nf + 2 * c;
            *(float2*)(outM + ra * KK + ca)       = make_float2(Mr[g][nf][0], Mr[g][nf][1]);
            *(float2*)(outM + (ra + 8) * KK + ca) = make_float2(Mr[g][nf][2], Mr[g][nf][3]);
        }
    if (lid == 0) {
        g_sc[b * CCH + ch] = s;
        g_ns[b * CCH + ch] = (float)ns;
    }

    // ---- FUSED COMBINE: 16th-arriving chunk CTA of batch b folds it ----
    __threadfence();
    int lastc = 0;
    if (lid == 0) lastc = (atomicAdd(&g_bdone[b], 1) == CCH - 1);
    lastc = __shfl_sync(0xffffffffu, lastc, 0);
    if (!lastc) return;

    if (lid == 0) g_bdone[b] = 0;   // reset for next graph replay
    __threadfence();                // acquire: all 16 chunks' stores visible

    const int j = lid;

    // prefetch chunk 0 matrix
    {
        const float* Mc = g_M + (size_t)(b * CCH) * (KK * KK);
#pragma unroll
        for (int k = 0; k < 8; k++)
            cp_async16(&Ms[0][j * 4 + k * 128], Mc + j * 4 + k * 128);
        CP_COMMIT();
    }

    // fused tree: joint partials + scales + step counts (len = 1 + sum ns)
    float num = (j < CCH) ? g_jnum[b * CCH + j] : 0.f;
    float scs = (j < CCH) ? g_sc[b * CCH + j] : 0.f;
    float nsf = (j < CCH) ? g_ns[b * CCH + j] : 0.f;
#pragma unroll
    for (int o = 16; o; o >>= 1) {
        num += __shfl_xor_sync(0xffffffffu, num, o);
        scs += __shfl_xor_sync(0xffffffffu, scs, o);
        nsf += __shfl_xor_sync(0xffffffffu, nsf, o);
    }
    const int len = 1 + (int)nsf;
    if (j == 0) num += endT[yb[len - 1]];

    // alpha0
    float a0 = startT[j] + g_logits[(size_t)b * TT * KK + j];
    float m = a0;
#pragma unroll
    for (int o = 16; o; o >>= 1) m = fmaxf(m, __shfl_xor_sync(0xffffffffu, m, o));
    float p = __expf(a0 - m);
    float sden = m + scs;   // all chunk scales folded up-front

    // fold the 16 chunk matrices
    for (int cc = 0; cc < CCH; cc++) {
        if (cc + 1 < CCH) {
            const float* Mn = g_M + (size_t)(b * CCH + cc + 1) * (KK * KK);
#pragma unroll
            for (int k = 0; k < 8; k++)
                cp_async16(&Ms[(cc + 1) & 1][j * 4 + k * 128], Mn + j * 4 + k * 128);
            CP_COMMIT();
            CP_WAIT1();
        } else {
            CP_WAIT0();
        }
        __syncwarp();

        const float* Mc = Ms[cc & 1];
        float r0 = 0.f, r1 = 0.f, r2 = 0.f, r3 = 0.f;
#pragma unroll
        for (int i = 0; i < KK; i += 4) {
            r0 = fmaf(__shfl_sync(0xffffffffu, p, i + 0), Mc[(i + 0) * KK + j], r0);
            r1 = fmaf(__shfl_sync(0xffffffffu, p, i + 1), Mc[(i + 1) * KK + j], r1);
            r2 = fmaf(__shfl_sync(0xffffffffu, p, i + 2), Mc[(i + 2) * KK + j], r2);
            r3 = fmaf(__shfl_sync(0xffffffffu, p, i + 3), Mc[(i + 3) * KK + j], r3);
        }
        p = (r0 + r1) + (r2 + r3);

        unsigned mxb = __reduce_max_sync(0xffffffffu, __float_as_uint(p));
        unsigned ee = mxb >> 23;
        p *= __uint_as_float((254u - ee) << 23);
        sden += (float)((int)ee - 127) * LN2F;
        __syncwarp();
    }

    float q = p * __expf(endT[j]);
#pragma unroll
    for (int o = 16; o; o >>= 1) q += __shfl_xor_sync(0xffffffffu, q, o);
    float den = sden + __logf(q);

    if (j == 0) g_partial[b] = num - den;

    // fused final reduction: last batch-combiner sums all partials
    __threadfence();
    int lastflag = 0;
    if (j == 0) lastflag = (atomicAdd(&g_done, 1) == BB - 1);
    lastflag = __shfl_sync(0xffffffffu, lastflag, 0);
    if (lastflag) {
        __threadfence();
        float vv = g_partial[j] + g_partial[j + 32];
#pragma unroll
        for (int o = 16; o; o >>= 1) vv += __shfl_xor_sync(0xffffffffu, vv, o);
        if (j == 0) {
            out[0] = -vv;
            g_done = 0;   // reset for next graph replay
        }
    }
}

// ---------------------------------------------------------------------------
extern "C" void kernel_launch(void* const* d_in, const int* in_sizes, int n_in,
                              void* d_out, int out_size) {
    const float*         X     = (const float*)d_in[0];
    const int*           y     = (const int*)d_in[1];
    const unsigned int*  mask  = (const unsigned int*)d_in[2];
    const float*         W     = (const float*)d_in[3];
    const float*         bias  = (const float*)d_in[4];
    const float*         trans = (const float*)d_in[5];
    const float*         stt   = (const float*)d_in[6];
    const float*         endt  = (const float*)d_in[7];
    float* out = (float*)d_out;

    wtrans_kernel<<<EE / 64, 256>>>(W);
    gemm_kernel<<<MM / RPB, 128>>>(X, bias, mask);
    chunk_kernel<<<BB * CCH, 32>>>(y, mask, trans, stt, endt, out);
}

// round 17
// speedup vs baseline: 1.3056x; 1.0292x over previous
#include <cuda_runtime.h>
#include <cuda_bf16.h>
#include <cstdint>

// Problem constants
#define BB 64
#define TT 512
#define EE 2048
#define KK 32
#define MM (BB * TT)
#define CCH 16          // chunks per sequence
#define SCH 32          // steps per chunk

// Scratch (device globals: no allocation allowed)
__device__ float g_logits[MM * KK];          // 4 MB raw logits
__device__ float g_exp[MM * KK];             // 4 MB exp(logits)
__device__ float g_Wt[KK * EE];              // W transposed (tf32-rounded): [n][e]
__device__ float g_M[BB * CCH * KK * KK];    // 4 MB chunk transfer matrices
__device__ float g_sc[BB * CCH];             // chunk log-scales
__device__ float g_ns[BB * CCH];             // chunk valid-step counts
__device__ float g_jnum[BB * CCH];           // chunk joint-score partials
__device__ float g_partial[BB];
__device__ int   g_done = 0;

// ---------------------------------------------------------------------------
// helpers
// ---------------------------------------------------------------------------
static __device__ __forceinline__ float tf32_round(float f) {
    uint32_t r;
    asm("cvt.rna.tf32.f32 %0, %1;" : "=r"(r) : "f"(f));
    return __uint_as_float(r);
}
static __device__ __forceinline__ void mma_tf32(float& c0, float& c1,
                                                float& c2, float& c3,
                                                uint32_t a0, uint32_t a1,
                                                uint32_t a2, uint32_t a3,
                                                uint32_t b0, uint32_t b1) {
    asm volatile(
        "mma.sync.aligned.m16n8k8.row.col.f32.tf32.tf32.f32 "
        "{%0,%1,%2,%3}, {%4,%5,%6,%7}, {%8,%9}, {%0,%1,%2,%3};\n"
        : "+f"(c0), "+f"(c1), "+f"(c2), "+f"(c3)
        : "r"(a0), "r"(a1), "r"(a2), "r"(a3), "r"(b0), "r"(b1));
}
// D = A*B + 0 (separate zero C input; D regs distinct)
static __device__ __forceinline__ void mma_tf32_z(float& d0, float& d1,
                                                  float& d2, float& d3,
                                                  uint32_t a0, uint32_t a1,
                                                  uint32_t a2, uint32_t a3,
                                                  uint32_t b0, uint32_t b1) {
    asm volatile(
        "mma.sync.aligned.m16n8k8.row.col.f32.tf32.tf32.f32 "
        "{%0,%1,%2,%3}, {%4,%5,%6,%7}, {%8,%9}, {%10,%11,%12,%13};\n"
        : "=f"(d0), "=f"(d1), "=f"(d2), "=f"(d3)
        : "r"(a0), "r"(a1), "r"(a2), "r"(a3), "r"(b0), "r"(b1),
          "f"(0.f), "f"(0.f), "f"(0.f), "f"(0.f));
}
static __device__ __forceinline__ void cp_async16(void* dst, const void* src) {
    unsigned sdst = (unsigned)__cvta_generic_to_shared(dst);
    asm volatile("cp.async.cg.shared.global [%0], [%1], 16;\n"
                 :: "r"(sdst), "l"(src));
}
#define CP_COMMIT() asm volatile("cp.async.commit_group;\n" ::: "memory")
#define CP_WAIT0()  asm volatile("cp.async.wait_group 0;\n" ::: "memory")
#define CP_WAIT1()  asm volatile("cp.async.wait_group 1;\n" ::: "memory")
#define LN2F 0.6931471805599453f

// ---------------------------------------------------------------------------
// W transpose pre-pass: g_Wt[n][e] = tf32_round(W[e][n])
// ---------------------------------------------------------------------------
__global__ void __launch_bounds__(256) wtrans_kernel(const float* __restrict__ W) {
    __shared__ float s[64][33];
    const int tid = threadIdx.x;
    const int e0 = blockIdx.x * 64;
#pragma unroll
    for (int l = 0; l < 8; l++) {
        int idx = tid + l * 256;
        int ep = idx >> 5, n = idx & 31;
        s[ep][n] = W[(size_t)(e0 + ep) * KK + n];
    }
    __syncthreads();
#pragma unroll
    for (int l = 0; l < 8; l++) {
        int idx = tid + l * 256;
        int n = idx >> 6, ep = idx & 63;
        g_Wt[(size_t)n * EE + e0 + ep] = tf32_round(s[ep][n]);
    }
}

// ---------------------------------------------------------------------------
// GEMM: logits = X @ W + b via mma.sync tf32; writes logits and exp(logits).
// FROZEN R12 structure (depth-2 cp.async, two syncs/tile) + mask CTA skip.
// ---------------------------------------------------------------------------
#define TE 32
#define RPB 128
#define XPITCH 36

__global__ void __launch_bounds__(128) gemm_kernel(const float* __restrict__ X,
                                                   const float* __restrict__ bias,
                                                   const unsigned int* __restrict__ mask) {
    const int row0 = blockIdx.x * RPB;
    // mask is a per-batch prefix: block fully dead iff first timestep masked.
    {
        const int b  = row0 >> 9;         // row0 / TT
        const int t0 = row0 & (TT - 1);
        if (t0 > 0 && mask[b * TT + t0] == 0u) return;
    }

    __shared__ __align__(16) float Xs[2][RPB][XPITCH];

    const int tid = threadIdx.x;
    const int wid = tid >> 5;
    const int lid = tid & 31;
    const int qr  = lid >> 2;
    const int c   = lid & 3;
    const int rw2 = wid * 32;
    const float* Xg = X + (size_t)row0 * EE;
    const int NT = EE / TE;

    float acc[2][4][4];
#pragma unroll
    for (int g = 0; g < 2; g++)
#pragma unroll
        for (int nf = 0; nf < 4; nf++)
#pragma unroll
            for (int u = 0; u < 4; u++) acc[g][nf][u] = 0.f;

    auto loadX = [&](int bi, int t) {
        const int e0 = t * TE;
#pragma unroll
        for (int l = 0; l < 8; l++) {
            int id = tid + l * 128;
            int r  = id >> 3;
            int ch = id & 7;
            cp_async16(&Xs[bi][r][ch * 4], Xg + (size_t)r * EE + e0 + ch * 4);
        }
    };
    auto loadB = [&](float2* Bf, int t) {
        const int e0 = t * TE;
#pragma unroll
        for (int ks = 0; ks < 4; ks++)
#pragma unroll
            for (int nf = 0; nf < 4; nf++)
                Bf[ks * 4 + nf] = *(const float2*)(g_Wt +
                    (size_t)(nf * 8 + qr) * EE + e0 + ks * 8 + 2 * c);
    };

    float2 B0f[16], B1f[16];
    loadX(0, 0); CP_COMMIT();
    loadX(1, 1); CP_COMMIT();
    loadB(B0f, 0);

    auto step = [&](int t, float2* Bcur, float2* Bnext) {
        loadB(Bnext, min(t + 1, NT - 1));
        if (t < NT - 1) { CP_WAIT1(); } else { CP_WAIT0(); }
        __syncthreads();

        const float (*Xt)[XPITCH] = Xs[t & 1];
#pragma unroll
        for (int ks = 0; ks < 4; ks++) {
            const int kp = ks * 8 + 2 * c;
            float2 x0 = *(const float2*)&Xt[rw2 + qr][kp];
            float2 x1 = *(const float2*)&Xt[rw2 + qr + 8][kp];
            float2 x2 = *(const float2*)&Xt[rw2 + qr + 16][kp];
            float2 x3 = *(const float2*)&Xt[rw2 + qr + 24][kp];
#pragma unroll
            for (int nf = 0; nf < 4; nf++) {
                float2 wv = Bcur[ks * 4 + nf];
                uint32_t b0 = __float_as_uint(wv.x);
                uint32_t b1 = __float_as_uint(wv.y);
                mma_tf32(acc[0][nf][0], acc[0][nf][1], acc[0][nf][2], acc[0][nf][3],
                         __float_as_uint(x0.x), __float_as_uint(x1.x),
                         __float_as_uint(x0.y), __float_as_uint(x1.y), b0, b1);
                mma_tf32(acc[1][nf][0], acc[1][nf][1], acc[1][nf][2], acc[1][nf][3],
                         __float_as_uint(x2.x), __float_as_uint(x3.x),
                         __float_as_uint(x2.y), __float_as_uint(x3.y), b0, b1);
            }
        }
        __syncthreads();
        if (t + 2 < NT) { loadX(t & 1, t + 2); CP_COMMIT(); }
    };

    for (int t = 0; t < NT; t += 2) {
        step(t, B0f, B1f);
        step(t + 1, B1f, B0f);
    }

    float bv0[4], bv1[4];
#pragma unroll
    for (int nf = 0; nf < 4; nf++) {
        bv0[nf] = __ldg(bias + nf * 8 + 2 * c);
        bv1[nf] = __ldg(bias + nf * 8 + 2 * c + 1);
    }
#pragma unroll
    for (int g = 0; g < 2; g++) {
        const int rowa = row0 + rw2 + qr + g * 16;
        const int rowb = rowa + 8;
        float* loA = g_logits + (size_t)rowa * KK;
        float* loB = g_logits + (size_t)rowb * KK;
        float* eoA = g_exp + (size_t)rowa * KK;
        float* eoB = g_exp + (size_t)rowb * KK;
#pragma unroll
        for (int nf = 0; nf < 4; nf++) {
            int j0 = nf * 8 + 2 * c;
            float2 va = make_float2(acc[g][nf][0] + bv0[nf], acc[g][nf][1] + bv1[nf]);
            float2 vb = make_float2(acc[g][nf][2] + bv0[nf], acc[g][nf][3] + bv1[nf]);
            *(float2*)(loA + j0) = va;
            *(float2*)(loB + j0) = vb;
            *(float2*)(eoA + j0) = make_float2(__expf(va.x), __expf(va.y));
            *(float2*)(eoB + j0) = make_float2(__expf(vb.x), __expf(vb.y));
        }
    }
}

// ---------------------------------------------------------------------------
// Chunk kernel: warp (b, ch) computes M_c = prod (ET . diag(e_t)) via
// register-resident mma.sync chains, AND this chunk's joint-score partial.
// R17: per-step B operands fed raw (HW truncates to tf32) — no per-step cvt.
// ---------------------------------------------------------------------------
__global__ void __launch_bounds__(32) chunk_kernel(const int* __restrict__ y,
                                                   const unsigned int* __restrict__ mask,
                                                   const float* __restrict__ trans,
                                                   const float* __restrict__ startT) {
    __shared__ __align__(16) float Es[SCH * KK];   // chunk emissions (4 KB)

    const int b  = blockIdx.x >> 4;
    const int ch = blockIdx.x & 15;
    const int lid = threadIdx.x;
    const int qr = lid >> 2;
    const int c  = lid & 3;
    const int t0 = ch * SCH + 1;

    // stage emissions for steps t0..t0+31 (rows clamped to <TT)
    const float* EB = g_exp + (size_t)b * TT * KK;
#pragma unroll
    for (int k = 0; k < 8; k++) {
        int f = lid + k * 32;
        int row = f >> 3;
        if (t0 + row < TT)
            cp_async16(&Es[f * 4], EB + (size_t)(t0 + row) * KK + (f & 7) * 4);
    }
    CP_COMMIT();

    const unsigned int* mk = mask + b * TT;
    const int* yb = y + b * TT;

    // ---- joint-score partial for timesteps tt = ch*32 + lid ----
    {
        const int tt = ch * SCH + lid;
        float jp = 0.f;
        if (mk[tt] != 0u) {
            int yt = yb[tt];
            jp = g_logits[(size_t)b * TT * KK + tt * KK + yt];
            if (tt > 0) jp += trans[yb[tt - 1] * KK + yt];
        }
#pragma unroll
        for (int o = 16; o; o >>= 1) jp += __shfl_xor_sync(0xffffffffu, jp, o);
        if (lid == 0) {
            if (ch == 0) jp += startT[yb[0]];
            g_jnum[b * CCH + ch] = jp;
        }
    }

    // ---- chunk-local valid-step count (mask is a prefix) ----
    int v = 0;
    if (t0 + lid < TT) v = (mk[t0 + lid] != 0u);
#pragma unroll
    for (int o = 16; o; o >>= 1) v += __shfl_xor_sync(0xffffffffu, v, o);
    const int ns = v;   // 0..32

    // static ET fragments (tf32-rounded once)
    float ETb0[4][4], ETb1[4][4];
#pragma unroll
    for (int ks = 0; ks < 4; ks++)
#pragma unroll
        for (int nf = 0; nf < 4; nf++) {
            ETb0[ks][nf] = tf32_round(__expf(trans[(8 * ks + 2 * c)     * KK + 8 * nf + qr]));
            ETb1[ks][nf] = tf32_round(__expf(trans[(8 * ks + 2 * c + 1) * KK + 8 * nf + qr]));
        }

    // M = I
    float Mr[2][4][4], Nr[2][4][4];
#pragma unroll
    for (int g = 0; g < 2; g++)
#pragma unroll
        for (int nf = 0; nf < 4; nf++) {
            int ra = 16 * g + qr, rb = ra + 8;
            int ca = 8 * nf + 2 * c, cb = ca + 1;
            Mr[g][nf][0] = (ra == ca) ? 1.f : 0.f;
            Mr[g][nf][1] = (ra == cb) ? 1.f : 0.f;
            Mr[g][nf][2] = (rb == ca) ? 1.f : 0.f;
            Mr[g][nf][3] = (rb == cb) ? 1.f : 0.f;
        }
    float s = 0.f;

    auto renormM = [&]() {
        float mx = 0.f;
#pragma unroll
        for (int g = 0; g < 2; g++)
#pragma unroll
            for (int nf = 0; nf < 4; nf++)
#pragma unroll
                for (int u = 0; u < 4; u++) mx = fmaxf(mx, Mr[g][nf][u]);
        unsigned mxb = __reduce_max_sync(0xffffffffu, __float_as_uint(mx));
        unsigned ee = mxb >> 23;
        float scf = __uint_as_float((254u - ee) << 23);
#pragma unroll
        for (int g = 0; g < 2; g++)
#pragma unroll
            for (int nf = 0; nf < 4; nf++)
#pragma unroll
                for (int u = 0; u < 4; u++) Mr[g][nf][u] *= scf;
        s += (float)((int)ee - 127) * LN2F;
    };

    if (ns > 0) {
        CP_WAIT0();
        __syncwarp();

        float eC[4], eN[4];
#pragma unroll
        for (int nf = 0; nf < 4; nf++) eC[nf] = Es[0 * KK + 8 * nf + qr];
        {
            int un = (ns > 1) ? 1 : 0;
#pragma unroll
            for (int nf = 0; nf < 4; nf++) eN[nf] = Es[un * KK + 8 * nf + qr];
        }

        // one scan step: DST = SRC * (ET . diag(e)); B fed raw fp32 bits
        // (tensor HW truncates to tf32 — removes 32 cvt per step).
        auto do_step = [&](float (&S)[2][4][4], float (&D)[2][4][4]) {
            float B0[4][4], B1[4][4];
#pragma unroll
            for (int ks = 0; ks < 4; ks++)
#pragma unroll
                for (int nf = 0; nf < 4; nf++) {
                    B0[ks][nf] = ETb0[ks][nf] * eC[nf];
                    B1[ks][nf] = ETb1[ks][nf] * eC[nf];
                }
#pragma unroll
            for (int g = 0; g < 2; g++)
#pragma unroll
                for (int nf = 0; nf < 4; nf++) {
                    mma_tf32_z(D[g][nf][0], D[g][nf][1], D[g][nf][2], D[g][nf][3],
                               __float_as_uint(S[g][0][0]), __float_as_uint(S[g][0][2]),
                               __float_as_uint(S[g][0][1]), __float_as_uint(S[g][0][3]),
                               __float_as_uint(B0[0][nf]), __float_as_uint(B1[0][nf]));
#pragma unroll
                    for (int ks = 1; ks < 4; ks++)
                        mma_tf32(D[g][nf][0], D[g][nf][1], D[g][nf][2], D[g][nf][3],
                                 __float_as_uint(S[g][ks][0]), __float_as_uint(S[g][ks][2]),
                                 __float_as_uint(S[g][ks][1]), __float_as_uint(S[g][ks][3]),
                                 __float_as_uint(B0[ks][nf]), __float_as_uint(B1[ks][nf]));
                }
        };

#pragma unroll 2
        for (int u = 0; u < ns; u++) {
            if (u & 1) do_step(Nr, Mr);
            else       do_step(Mr, Nr);
#pragma unroll
            for (int nf = 0; nf < 4; nf++) eC[nf] = eN[nf];
            int un = u + 2 < ns ? u + 2 : (ns - 1);
#pragma unroll
            for (int nf = 0; nf < 4; nf++) eN[nf] = Es[un * KK + 8 * nf + qr];
            if (((u + 1) & 7) == 0) renormM();
        }
        if (ns & 1) {
#pragma unroll
            for (int g = 0; g < 2; g++)
#pragma unroll
                for (int nf = 0; nf < 4; nf++)
#pragma unroll
                    for (int u = 0; u < 4; u++) Mr[g][nf][u] = Nr[g][nf][u];
        }
    } else {
        CP_WAIT0();
    }

    // store M_c, scale, and step count
    float* out = g_M + (size_t)(b * CCH + ch) * (KK * KK);
#pragma unroll
    for (int g = 0; g < 2; g++)
#pragma unroll
        for (int nf = 0; nf < 4; nf++) {
            int ra = 16 * g + qr, ca = 8 * nf + 2 * c;
            *(float2*)(out + ra * KK + ca)       = make_float2(Mr[g][nf][0], Mr[g][nf][1]);
            *(float2*)(out + (ra + 8) * KK + ca) = make_float2(Mr[g][nf][2], Mr[g][nf][3]);
        }
    if (lid == 0) {
        g_sc[b * CCH + ch] = s;
        g_ns[b * CCH + ch] = (float)ns;
    }
}

// ---------------------------------------------------------------------------
// Combine kernel: one warp per batch. Sum joint partials (+ derive len from
// chunk step counts) + fold 16 chunk matrices + final logsumexp + reduction.
// (exact R12 version)
// ---------------------------------------------------------------------------
__global__ void __launch_bounds__(32) combine_kernel(const int* __restrict__ y,
                                                     const float* __restrict__ startT,
                                                     const float* __restrict__ endT,
                                                     float* __restrict__ out) {
    __shared__ __align__(16) float Ms[2][KK * KK];

    const int b = blockIdx.x;
    const int j = threadIdx.x;
    const int* yb = y + b * TT;

    // prefetch chunk 0 matrix
    {
        const float* Mc = g_M + (size_t)(b * CCH) * (KK * KK);
#pragma unroll
        for (int k = 0; k < 8; k++)
            cp_async16(&Ms[0][j * 4 + k * 128], Mc + j * 4 + k * 128);
        CP_COMMIT();
    }

    // fused tree: joint partials + scales + step counts (len = 1 + sum ns)
    float num = (j < CCH) ? g_jnum[b * CCH + j] : 0.f;
    float scs = (j < CCH) ? g_sc[b * CCH + j] : 0.f;
    float nsf = (j < CCH) ? g_ns[b * CCH + j] : 0.f;
#pragma unroll
    for (int o = 16; o; o >>= 1) {
        num += __shfl_xor_sync(0xffffffffu, num, o);
        scs += __shfl_xor_sync(0xffffffffu, scs, o);
        nsf += __shfl_xor_sync(0xffffffffu, nsf, o);
    }
    const int len = 1 + (int)nsf;
    if (j == 0) num += endT[yb[len - 1]];

    // alpha0
    float a0 = startT[j] + g_logits[(size_t)b * TT * KK + j];
    float m = a0;
#pragma unroll
    for (int o = 16; o; o >>= 1) m = fmaxf(m, __shfl_xor_sync(0xffffffffu, m, o));
    float p = __expf(a0 - m);
    float s = m + scs;    // all chunk scales folded up-front

    // fold the 16 chunk matrices
    for (int ch = 0; ch < CCH; ch++) {
        if (ch + 1 < CCH) {
            const float* Mn = g_M + (size_t)(b * CCH + ch + 1) * (KK * KK);
#pragma unroll
            for (int k = 0; k < 8; k++)
                cp_async16(&Ms[(ch + 1) & 1][j * 4 + k * 128], Mn + j * 4 + k * 128);
            CP_COMMIT();
            CP_WAIT1();
        } else {
            CP_WAIT0();
        }
        __syncwarp();

        const float* Mc = Ms[ch & 1];
        float r0 = 0.f, r1 = 0.f, r2 = 0.f, r3 = 0.f;
#pragma unroll
        for (int i = 0; i < KK; i += 4) {
            r0 = fmaf(__shfl_sync(0xffffffffu, p, i + 0), Mc[(i + 0) * KK + j], r0);
            r1 = fmaf(__shfl_sync(0xffffffffu, p, i + 1), Mc[(i + 1) * KK + j], r1);
            r2 = fmaf(__shfl_sync(0xffffffffu, p, i + 2), Mc[(i + 2) * KK + j], r2);
            r3 = fmaf(__shfl_sync(0xffffffffu, p, i + 3), Mc[(i + 3) * KK + j], r3);
        }
        p = (r0 + r1) + (r2 + r3);

        unsigned mxb = __reduce_max_sync(0xffffffffu, __float_as_uint(p));
        unsigned ee = mxb >> 23;
        p *= __uint_as_float((254u - ee) << 23);
        s += (float)((int)ee - 127) * LN2F;
        __syncwarp();
    }

    float q = p * __expf(endT[j]);
#pragma unroll
    for (int o = 16; o; o >>= 1) q += __shfl_xor_sync(0xffffffffu, q, o);
    float den = s + __logf(q);

    if (j == 0) g_partial[b] = num - den;

    // fused final reduction: last CTA sums all partials
    __threadfence();
    int lastflag = 0;
    if (j == 0) lastflag = (atomicAdd(&g_done, 1) == BB - 1);
    lastflag = __shfl_sync(0xffffffffu, lastflag, 0);
    if (lastflag) {
        __threadfence();
        float v = g_partial[j] + g_partial[j + 32];
#pragma unroll
        for (int o = 16; o; o >>= 1) v += __shfl_xor_sync(0xffffffffu, v, o);
        if (j == 0) {
            out[0] = -v;
            g_done = 0;   // reset for next graph replay
        }
    }
}

// ---------------------------------------------------------------------------
extern "C" void kernel_launch(void* const* d_in, const int* in_sizes, int n_in,
                              void* d_out, int out_size) {
    const float*         X     = (const float*)d_in[0];
    const int*           y     = (const int*)d_in[1];
    const unsigned int*  mask  = (const unsigned int*)d_in[2];
    const float*         W     = (const float*)d_in[3];
    const float*         bias  = (const float*)d_in[4];
    const float*         trans = (const float*)d_in[5];
    const float*         stt   = (const float*)d_in[6];
    const float*         endt  = (const float*)d_in[7];
    float* out = (float*)d_out;

    wtrans_kernel<<<EE / 64, 256>>>(W);
    gemm_kernel<<<MM / RPB, 128>>>(X, bias, mask);
    chunk_kernel<<<BB * CCH, 32>>>(y, mask, trans, stt);
    combine_kernel<<<BB, 32>>>(y, stt, endt, out);
}